// round 3
// baseline (speedup 1.0000x reference)
#include <cuda_runtime.h>
#include <cuda_bf16.h>
#include <cstdint>

// Problem constants
#define SQ   2048
#define BB   2
#define HID  4096
#define NH   32
#define HD   128
#define NG   2
#define QKVN 4608      // NH*HD + 2*NG*HD
#define MTOK 4096      // SQ*B tokens

// ------------------------- scratch (device globals) -------------------------
__device__ float g_mixed[(size_t)MTOK * QKVN];          // 75.5 MB
__device__ float g_Q[(size_t)BB * NH * SQ * HD];        // 67 MB
__device__ float g_K[(size_t)BB * NG * SQ * HD];        // 4.2 MB
__device__ float g_V[(size_t)BB * NG * SQ * HD];        // 4.2 MB
__device__ float g_ctx[(size_t)MTOK * HID];             // 67 MB

// ------------------------- SGEMM: C = A@B (+bias) ---------------------------
// A [M,K] row-major, B [K,N] row-major. BM=BN=128, BK=16, 256 thr, 8x8/thread.
// All dims must be multiples of tile sizes (they are: 4096/4608).
template<bool BIAS>
__global__ __launch_bounds__(256) void sgemm_kernel(
    const float* __restrict__ A, const float* __restrict__ B,
    const float* __restrict__ bias, float* __restrict__ C,
    int M, int N, int K)
{
    __shared__ float As[16][128];   // transposed: As[kk][m]
    __shared__ float Bs[16][128];

    const int t  = threadIdx.x;
    const int tx = t % 16;          // col group
    const int ty = t / 16;          // row group
    const int m0 = blockIdx.y * 128;
    const int n0 = blockIdx.x * 128;

    float acc[8][8];
    #pragma unroll
    for (int i = 0; i < 8; i++)
        #pragma unroll
        for (int j = 0; j < 8; j++) acc[i][j] = 0.f;

    const int a_row = t / 4;            // 0..63
    const int a_col = (t % 4) * 4;      // 0,4,8,12
    const int b_row = t / 32;           // 0..7
    const int b_col = (t % 32) * 4;     // 0..124

    const float* Aptr = A + (size_t)(m0 + a_row) * K + a_col;
    const float* Bptr = B + (size_t)b_row * N + (n0 + b_col);

    for (int k0 = 0; k0 < K; k0 += 16) {
        #pragma unroll
        for (int i = 0; i < 2; i++) {
            float4 v = *(const float4*)(Aptr + (size_t)i * 64 * K + k0);
            As[a_col + 0][a_row + i * 64] = v.x;
            As[a_col + 1][a_row + i * 64] = v.y;
            As[a_col + 2][a_row + i * 64] = v.z;
            As[a_col + 3][a_row + i * 64] = v.w;
        }
        #pragma unroll
        for (int i = 0; i < 2; i++) {
            *(float4*)&Bs[b_row + i * 8][b_col] =
                *(const float4*)(Bptr + (size_t)(k0 + i * 8) * N);
        }
        __syncthreads();

        #pragma unroll
        for (int kk = 0; kk < 16; kk++) {
            float a[8], b[8];
            *(float4*)&a[0] = *(const float4*)&As[kk][ty * 8];
            *(float4*)&a[4] = *(const float4*)&As[kk][ty * 8 + 4];
            *(float4*)&b[0] = *(const float4*)&Bs[kk][tx * 8];
            *(float4*)&b[4] = *(const float4*)&Bs[kk][tx * 8 + 4];
            #pragma unroll
            for (int i = 0; i < 8; i++)
                #pragma unroll
                for (int j = 0; j < 8; j++)
                    acc[i][j] += a[i] * b[j];
        }
        __syncthreads();
    }

    #pragma unroll
    for (int i = 0; i < 8; i++) {
        const int m = m0 + ty * 8 + i;
        #pragma unroll
        for (int j = 0; j < 8; j += 4) {
            const int n = n0 + tx * 8 + j;
            float4 v;
            v.x = acc[i][j]; v.y = acc[i][j+1]; v.z = acc[i][j+2]; v.w = acc[i][j+3];
            if (BIAS) {
                v.x += bias[n]; v.y += bias[n+1]; v.z += bias[n+2]; v.w += bias[n+3];
            }
            *(float4*)&C[(size_t)m * N + n] = v;
        }
    }
}

// ------------------- rotary + repack (mixed -> Q/K/V) -----------------------
// rope: [SQ][32][2] (cos,sin). Q: [b][h][s][d], K/V: [b][g][s][d].
__global__ void rotary_repack_kernel(
    const float* __restrict__ mixed, const float* __restrict__ rope,
    float* __restrict__ Q, float* __restrict__ Kd, float* __restrict__ Vd)
{
    const int m  = blockIdx.x;          // token 0..4095 (= s*B + b)
    const int hh = blockIdx.y;          // 0..35
    const int s  = m >> 1;
    const int b  = m & 1;
    const int d  = threadIdx.x;         // 0..127

    const float* src;
    float* dst;
    bool rot;
    if (hh < NH) {
        src = mixed + (size_t)m * QKVN + hh * HD;
        dst = Q + ((size_t)(b * NH + hh) * SQ + s) * HD;
        rot = true;
    } else if (hh < NH + NG) {
        const int g = hh - NH;
        src = mixed + (size_t)m * QKVN + NH * HD + g * HD;
        dst = Kd + ((size_t)(b * NG + g) * SQ + s) * HD;
        rot = true;
    } else {
        const int g = hh - NH - NG;
        src = mixed + (size_t)m * QKVN + NH * HD + NG * HD + g * HD;
        dst = Vd + ((size_t)(b * NG + g) * SQ + s) * HD;
        rot = false;
    }

    if (!rot) { dst[d] = src[d]; return; }

    if (d < 32) {                       // pair p = d handles dims (2p, 2p+1)
        const float x0 = src[2 * d];
        const float x1 = src[2 * d + 1];
        const float c  = rope[(size_t)s * 64 + 2 * d];
        const float sn = rope[(size_t)s * 64 + 2 * d + 1];
        dst[2 * d]     = x0 * c - x1 * sn;
        dst[2 * d + 1] = x1 * c + x0 * sn;
    } else if (d >= 64) {
        dst[d] = src[d];
    }
}

// ------------------------- flash attention (fp32) ---------------------------
// grid (SQ/64, NH, B), 256 threads. BM=BN=64, causal; out ctx [s][b][h*HD+d].
#define FA_SMEM_FLOATS (128*68 + 128*68 + 64*128 + 64*68 + 192)

__global__ __launch_bounds__(256) void flash_kernel(
    const float* __restrict__ Q, const float* __restrict__ K,
    const float* __restrict__ V, float* __restrict__ O)
{
    extern __shared__ float smf[];
    float* Qt   = smf;                   // [128][68]  Qt[d][r]
    float* Kt   = Qt + 128 * 68;         // [128][68]  Kt[d][c]
    float* Vs   = Kt + 128 * 68;         // [64][128]  Vs[c][d]
    float* St   = Vs + 64 * 128;         // [64][68]   St[c][r]  (S transposed)
    float* mrow = St + 64 * 68;
    float* lrow = mrow + 64;
    float* alph = lrow + 64;

    const int t  = threadIdx.x;
    const int qt = blockIdx.x;           // query tile
    const int h  = blockIdx.y;
    const int b  = blockIdx.z;
    const int g  = h >> 4;               // rep = NH/NG = 16
    const int i0 = qt * 64;

    const float* Qb = Q + ((size_t)(b * NH + h) * SQ + i0) * HD;
    const float* Kb = K + ((size_t)(b * NG + g) * SQ) * HD;
    const float* Vb = V + ((size_t)(b * NG + g) * SQ) * HD;

    // load Q tile transposed
    for (int idx = t; idx < 64 * 32; idx += 256) {
        const int r  = idx >> 5;
        const int d4 = (idx & 31) * 4;
        float4 v = *(const float4*)(Qb + (size_t)r * HD + d4);
        Qt[(d4 + 0) * 68 + r] = v.x;
        Qt[(d4 + 1) * 68 + r] = v.y;
        Qt[(d4 + 2) * 68 + r] = v.z;
        Qt[(d4 + 3) * 68 + r] = v.w;
    }
    if (t < 64) { mrow[t] = -1e30f; lrow[t] = 0.f; }

    float acc[4][8];
    #pragma unroll
    for (int i = 0; i < 4; i++)
        #pragma unroll
        for (int j = 0; j < 8; j++) acc[i][j] = 0.f;

    const float scale = 0.08838834764831845f;   // 1/sqrt(128)
    const int tx1 = t % 16;
    const int ty1 = t / 16;

    for (int kt = 0; kt <= qt; kt++) {
        const int j0 = kt * 64;

        for (int idx = t; idx < 64 * 32; idx += 256) {
            const int r  = idx >> 5;
            const int d4 = (idx & 31) * 4;
            float4 v = *(const float4*)(Kb + (size_t)(j0 + r) * HD + d4);
            Kt[(d4 + 0) * 68 + r] = v.x;
            Kt[(d4 + 1) * 68 + r] = v.y;
            Kt[(d4 + 2) * 68 + r] = v.z;
            Kt[(d4 + 3) * 68 + r] = v.w;
            float4 w = *(const float4*)(Vb + (size_t)(j0 + r) * HD + d4);
            *(float4*)&Vs[r * 128 + d4] = w;
        }
        __syncthreads();

        // GEMM1: S[r][c] = sum_d Qt[d][r]*Kt[d][c]; rows ty1*4, cols tx1*4
        float s4[4][4];
        #pragma unroll
        for (int i = 0; i < 4; i++)
            #pragma unroll
            for (int j = 0; j < 4; j++) s4[i][j] = 0.f;

        #pragma unroll 8
        for (int kk = 0; kk < 128; kk++) {
            float a[4], bb[4];
            *(float4*)a  = *(const float4*)&Qt[kk * 68 + ty1 * 4];
            *(float4*)bb = *(const float4*)&Kt[kk * 68 + tx1 * 4];
            #pragma unroll
            for (int i = 0; i < 4; i++)
                #pragma unroll
                for (int j = 0; j < 4; j++)
                    s4[i][j] += a[i] * bb[j];
        }
        #pragma unroll
        for (int j = 0; j < 4; j++)
            #pragma unroll
            for (int i = 0; i < 4; i++)
                St[(tx1 * 4 + j) * 68 + (ty1 * 4 + i)] = s4[i][j] * scale;
        __syncthreads();

        // online softmax: one thread per row (threads 0..63)
        if (t < 64) {
            const int r = t;
            const float mold = mrow[r];
            float mnew = mold;
            float sum  = 0.f;
            if (kt == qt) {
                const int jmax = r;     // j0==i0: keep j <= r
                for (int j = 0; j <= jmax; j++)
                    mnew = fmaxf(mnew, St[j * 68 + r]);
                for (int j = 0; j < 64; j++) {
                    const float p = (j <= jmax) ? __expf(St[j * 68 + r] - mnew) : 0.f;
                    St[j * 68 + r] = p;
                    sum += p;
                }
            } else {
                for (int j = 0; j < 64; j++)
                    mnew = fmaxf(mnew, St[j * 68 + r]);
                for (int j = 0; j < 64; j++) {
                    const float p = __expf(St[j * 68 + r] - mnew);
                    St[j * 68 + r] = p;
                    sum += p;
                }
            }
            const float al = __expf(mold - mnew);
            lrow[r] = lrow[r] * al + sum;
            mrow[r] = mnew;
            alph[r] = al;
        }
        __syncthreads();

        // GEMM2: acc = acc*alpha + P @ V ; rows ty1*4, cols tx1*8
        float al[4];
        #pragma unroll
        for (int i = 0; i < 4; i++) al[i] = alph[ty1 * 4 + i];
        #pragma unroll
        for (int i = 0; i < 4; i++)
            #pragma unroll
            for (int j = 0; j < 8; j++) acc[i][j] *= al[i];

        #pragma unroll 4
        for (int j = 0; j < 64; j++) {
            float a[4];
            *(float4*)a = *(const float4*)&St[j * 68 + ty1 * 4];
            float bv[8];
            *(float4*)&bv[0] = *(const float4*)&Vs[j * 128 + tx1 * 8];
            *(float4*)&bv[4] = *(const float4*)&Vs[j * 128 + tx1 * 8 + 4];
            #pragma unroll
            for (int i = 0; i < 4; i++)
                #pragma unroll
                for (int jj = 0; jj < 8; jj++)
                    acc[i][jj] += a[i] * bv[jj];
        }
        __syncthreads();
    }

    // write ctx: O[((i0+r)*B + b)*HID + h*HD + d]
    #pragma unroll
    for (int i = 0; i < 4; i++) {
        const int r = ty1 * 4 + i;
        const float inv = 1.f / lrow[r];
        float* op = O + ((size_t)(i0 + r) * BB + b) * HID + h * HD + tx1 * 8;
        float4 v0, v1;
        v0.x = acc[i][0] * inv; v0.y = acc[i][1] * inv;
        v0.z = acc[i][2] * inv; v0.w = acc[i][3] * inv;
        v1.x = acc[i][4] * inv; v1.y = acc[i][5] * inv;
        v1.z = acc[i][6] * inv; v1.w = acc[i][7] * inv;
        *(float4*)(op)     = v0;
        *(float4*)(op + 4) = v1;
    }
}

// ------------------------------- launch -------------------------------------
extern "C" void kernel_launch(void* const* d_in, const int* in_sizes, int n_in,
                              void* d_out, int out_size)
{
    const float* hidden = (const float*)d_in[0];
    // d_in[1] = attention_mask (causal triu, known statically; unused)
    const float* rope    = (const float*)d_in[2];
    const float* W_qkv   = (const float*)d_in[3];
    const float* b_qkv   = (const float*)d_in[4];
    const float* W_dense = (const float*)d_in[5];
    float* out = (float*)d_out;

    float *mixed, *Qb, *Kb, *Vb, *ctx;
    cudaGetSymbolAddress((void**)&mixed, g_mixed);
    cudaGetSymbolAddress((void**)&Qb,    g_Q);
    cudaGetSymbolAddress((void**)&Kb,    g_K);
    cudaGetSymbolAddress((void**)&Vb,    g_V);
    cudaGetSymbolAddress((void**)&ctx,   g_ctx);

    static const size_t fa_smem = FA_SMEM_FLOATS * sizeof(float);
    cudaFuncSetAttribute(flash_kernel,
                         cudaFuncAttributeMaxDynamicSharedMemorySize,
                         (int)fa_smem);

    // 1) mixed = hidden @ W_qkv + b_qkv
    {
        dim3 grid(QKVN / 128, MTOK / 128);
        sgemm_kernel<true><<<grid, 256>>>(hidden, W_qkv, b_qkv, mixed,
                                          MTOK, QKVN, HID);
    }
    // 2) rotary + repack
    {
        dim3 grid(MTOK, NH + 2 * NG);
        rotary_repack_kernel<<<grid, 128>>>(mixed, rope, Qb, Kb, Vb);
    }
    // 3) flash attention -> ctx
    {
        dim3 grid(SQ / 64, NH, BB);
        flash_kernel<<<grid, 256, fa_smem>>>(Qb, Kb, Vb, ctx);
    }
    // 4) out = ctx @ W_dense
    {
        dim3 grid(HID / 128, MTOK / 128);
        sgemm_kernel<false><<<grid, 256>>>(ctx, W_dense, nullptr, out,
                                           MTOK, HID, HID);
    }
}

// round 6
// speedup vs baseline: 2.2523x; 2.2523x over previous
#include <cuda_runtime.h>
#include <cuda_bf16.h>
#include <cstdint>

// Problem constants
#define SQ   2048
#define BB   2
#define HID  4096
#define NH   32
#define HD   128
#define NG   2
#define QKVN 4608      // NH*HD + 2*NG*HD
#define MTOK 4096      // SQ*B tokens

// ------------------------- scratch (device globals) -------------------------
__device__ float g_mixed[(size_t)MTOK * QKVN];
__device__ float g_Q[(size_t)BB * NH * SQ * HD];
__device__ float g_K[(size_t)BB * NG * SQ * HD];
__device__ float g_V[(size_t)BB * NG * SQ * HD];
__device__ float g_ctx[(size_t)MTOK * HID];

// --------------------------- tf32 helpers -----------------------------------
__device__ __forceinline__ float to_tf32(float x) {
    uint32_t r;
    asm("cvt.rna.tf32.f32 %0, %1;" : "=r"(r) : "f"(x));
    return __uint_as_float(r);
}

// D += A@B ; m16n8k8 tf32
__device__ __forceinline__ void mma_tf32(float* c, const uint32_t* a, const uint32_t* b) {
    asm volatile(
        "mma.sync.aligned.m16n8k8.row.col.f32.tf32.tf32.f32 "
        "{%0,%1,%2,%3},{%4,%5,%6,%7},{%8,%9},{%0,%1,%2,%3};"
        : "+f"(c[0]), "+f"(c[1]), "+f"(c[2]), "+f"(c[3])
        : "r"(a[0]), "r"(a[1]), "r"(a[2]), "r"(a[3]),
          "r"(b[0]), "r"(b[1]));
}

// ------------------------- tf32 tensor-core GEMM ----------------------------
// C = A@B (+bias). A [M,K] row-major, B [K,N] row-major.
// 128x128 block, BK=32, 256 thr (8 warps, 4m x 2n), warp tile 32x64.
template<bool BIAS>
__global__ __launch_bounds__(256) void mma_gemm_kernel(
    const float* __restrict__ A, const float* __restrict__ B,
    const float* __restrict__ bias, float* __restrict__ C,
    int M, int N, int K)
{
    __shared__ __align__(16) float Am[128][36];    // [m][k], stride 36 (A-frag safe)
    __shared__ __align__(16) float Bs[32][136];    // [k][n], stride 136 (B-frag safe)

    const int t    = threadIdx.x;
    const int w    = t >> 5;
    const int lane = t & 31;
    const int g    = lane >> 2;
    const int tig  = lane & 3;
    const int warp_m = w & 3;       // 0..3 -> 32-row strip
    const int warp_n = w >> 2;      // 0..1 -> 64-col strip
    const int m0 = blockIdx.y * 128;
    const int n0 = blockIdx.x * 128;

    float acc[2][8][4];
    #pragma unroll
    for (int mt = 0; mt < 2; mt++)
        #pragma unroll
        for (int nt = 0; nt < 8; nt++)
            #pragma unroll
            for (int i = 0; i < 4; i++) acc[mt][nt][i] = 0.f;

    const int arow = t >> 3;            // 0..31
    const int acol = (t & 7) * 4;       // 0..28
    const int brow = t >> 5;            // 0..7
    const int bcol = (t & 31) * 4;      // 0..124

    for (int k0 = 0; k0 < K; k0 += 32) {
        #pragma unroll
        for (int p = 0; p < 4; p++) {
            float4 v = *(const float4*)(A + (size_t)(m0 + arow + p * 32) * K + k0 + acol);
            float4 tv = make_float4(to_tf32(v.x), to_tf32(v.y), to_tf32(v.z), to_tf32(v.w));
            *(float4*)&Am[arow + p * 32][acol] = tv;
        }
        #pragma unroll
        for (int p = 0; p < 4; p++) {
            float4 v = *(const float4*)(B + (size_t)(k0 + brow + p * 8) * N + n0 + bcol);
            float4 tv = make_float4(to_tf32(v.x), to_tf32(v.y), to_tf32(v.z), to_tf32(v.w));
            *(float4*)&Bs[brow + p * 8][bcol] = tv;
        }
        __syncthreads();

        #pragma unroll
        for (int ks = 0; ks < 4; ks++) {
            const int kk = ks * 8;
            uint32_t a[2][4], bf[8][2];
            #pragma unroll
            for (int mt = 0; mt < 2; mt++) {
                const int r = warp_m * 32 + mt * 16;
                a[mt][0] = __float_as_uint(Am[r + g    ][kk + tig]);
                a[mt][1] = __float_as_uint(Am[r + g + 8][kk + tig]);
                a[mt][2] = __float_as_uint(Am[r + g    ][kk + tig + 4]);
                a[mt][3] = __float_as_uint(Am[r + g + 8][kk + tig + 4]);
            }
            #pragma unroll
            for (int nt = 0; nt < 8; nt++) {
                const int c = warp_n * 64 + nt * 8 + g;
                bf[nt][0] = __float_as_uint(Bs[kk + tig    ][c]);
                bf[nt][1] = __float_as_uint(Bs[kk + tig + 4][c]);
            }
            #pragma unroll
            for (int mt = 0; mt < 2; mt++)
                #pragma unroll
                for (int nt = 0; nt < 8; nt++)
                    mma_tf32(acc[mt][nt], a[mt], bf[nt]);
        }
        __syncthreads();
    }

    #pragma unroll
    for (int mt = 0; mt < 2; mt++) {
        const int r0 = m0 + warp_m * 32 + mt * 16 + g;
        #pragma unroll
        for (int nt = 0; nt < 8; nt++) {
            const int col = n0 + warp_n * 64 + nt * 8 + tig * 2;
            float b0 = 0.f, b1 = 0.f;
            if (BIAS) { b0 = bias[col]; b1 = bias[col + 1]; }
            float2 v0 = make_float2(acc[mt][nt][0] + b0, acc[mt][nt][1] + b1);
            float2 v1 = make_float2(acc[mt][nt][2] + b0, acc[mt][nt][3] + b1);
            *(float2*)&C[(size_t)r0 * N + col]       = v0;
            *(float2*)&C[(size_t)(r0 + 8) * N + col] = v1;
        }
    }
}

// ------------------- rotary + repack (mixed -> Q/K/V) -----------------------
__global__ void rotary_repack_kernel(
    const float* __restrict__ mixed, const float* __restrict__ rope,
    float* __restrict__ Q, float* __restrict__ Kd, float* __restrict__ Vd)
{
    const int m  = blockIdx.x;
    const int hh = blockIdx.y;
    const int s  = m >> 1;
    const int b  = m & 1;
    const int d  = threadIdx.x;

    const float* src;
    float* dst;
    bool rot;
    if (hh < NH) {
        src = mixed + (size_t)m * QKVN + hh * HD;
        dst = Q + ((size_t)(b * NH + hh) * SQ + s) * HD;
        rot = true;
    } else if (hh < NH + NG) {
        const int gg = hh - NH;
        src = mixed + (size_t)m * QKVN + NH * HD + gg * HD;
        dst = Kd + ((size_t)(b * NG + gg) * SQ + s) * HD;
        rot = true;
    } else {
        const int gg = hh - NH - NG;
        src = mixed + (size_t)m * QKVN + NH * HD + NG * HD + gg * HD;
        dst = Vd + ((size_t)(b * NG + gg) * SQ + s) * HD;
        rot = false;
    }

    if (!rot) { dst[d] = src[d]; return; }

    if (d < 32) {
        const float x0 = src[2 * d];
        const float x1 = src[2 * d + 1];
        const float c  = rope[(size_t)s * 64 + 2 * d];
        const float sn = rope[(size_t)s * 64 + 2 * d + 1];
        dst[2 * d]     = x0 * c - x1 * sn;
        dst[2 * d + 1] = x1 * c + x0 * sn;
    } else if (d >= 64) {
        dst[d] = src[d];
    }
}

// --------------------- flash attention (tf32 mma) ---------------------------
// BM=BN=64, 256 threads (8 warps: 4m x 2n). grid (SQ/64, NH, B).
#define QS_STR 132
#define KS_STR 132
#define VS_STR 136
#define PS_STR 68
#define FA_SMEM_FLOATS (64*QS_STR + 64*KS_STR + 64*VS_STR + 64*PS_STR + 192)

__global__ __launch_bounds__(256) void flash_mma_kernel(
    const float* __restrict__ Q, const float* __restrict__ K,
    const float* __restrict__ V, float* __restrict__ O)
{
    extern __shared__ __align__(16) float smf[];
    float* Qs   = smf;
    float* Ks   = Qs + 64 * QS_STR;
    float* Vs   = Ks + 64 * KS_STR;
    float* Ps   = Vs + 64 * VS_STR;
    float* mrow = Ps + 64 * PS_STR;
    float* lrow = mrow + 64;
    float* alph = lrow + 64;

    const int t    = threadIdx.x;
    const int w    = t >> 5;
    const int lane = t & 31;
    const int g    = lane >> 2;
    const int tig  = lane & 3;
    const int warp_m = w & 3;       // 16-row strip of S / O
    const int warp_n = w >> 2;      // 32-col strip of S, 64-col strip of O
    const int qt = blockIdx.x;
    const int h  = blockIdx.y;
    const int b  = blockIdx.z;
    const int gk = h >> 4;          // rep = 16
    const int i0 = qt * 64;

    const float* Qb = Q + ((size_t)(b * NH + h) * SQ + i0) * HD;
    const float* Kb = K + ((size_t)(b * NG + gk) * SQ) * HD;
    const float* Vb = V + ((size_t)(b * NG + gk) * SQ) * HD;

    // load Q tile (row-major, tf32-rounded)
    {
        const int r0 = t >> 5, c = (t & 31) * 4;
        #pragma unroll
        for (int p = 0; p < 8; p++) {
            const int r = r0 + p * 8;
            float4 v = *(const float4*)(Qb + (size_t)r * HD + c);
            float4 tv = make_float4(to_tf32(v.x), to_tf32(v.y), to_tf32(v.z), to_tf32(v.w));
            *(float4*)&Qs[r * QS_STR + c] = tv;
        }
    }
    if (t < 64) { mrow[t] = -1e30f; lrow[t] = 0.f; }

    float oacc[8][4];
    #pragma unroll
    for (int nt = 0; nt < 8; nt++)
        #pragma unroll
        for (int i = 0; i < 4; i++) oacc[nt][i] = 0.f;

    const float scale = 0.08838834764831845f;   // 1/sqrt(128)

    for (int kt = 0; kt <= qt; kt++) {
        const int j0 = kt * 64;

        // load K & V tiles
        {
            const int r0 = t >> 5, c = (t & 31) * 4;
            #pragma unroll
            for (int p = 0; p < 8; p++) {
                const int r = r0 + p * 8;
                float4 kv = *(const float4*)(Kb + (size_t)(j0 + r) * HD + c);
                *(float4*)&Ks[r * KS_STR + c] =
                    make_float4(to_tf32(kv.x), to_tf32(kv.y), to_tf32(kv.z), to_tf32(kv.w));
                float4 vv = *(const float4*)(Vb + (size_t)(j0 + r) * HD + c);
                *(float4*)&Vs[r * VS_STR + c] =
                    make_float4(to_tf32(vv.x), to_tf32(vv.y), to_tf32(vv.z), to_tf32(vv.w));
            }
        }
        __syncthreads();

        // GEMM1: S(64x64) = Q @ K^T, K-dim = HD = 128 (16 k-steps)
        float s4[4][4];
        #pragma unroll
        for (int nt = 0; nt < 4; nt++)
            #pragma unroll
            for (int i = 0; i < 4; i++) s4[nt][i] = 0.f;

        #pragma unroll
        for (int ks = 0; ks < 16; ks++) {
            const int kk = ks * 8;
            uint32_t qa[4], kb2[4][2];
            const int r = warp_m * 16;
            qa[0] = __float_as_uint(Qs[(r + g    ) * QS_STR + kk + tig]);
            qa[1] = __float_as_uint(Qs[(r + g + 8) * QS_STR + kk + tig]);
            qa[2] = __float_as_uint(Qs[(r + g    ) * QS_STR + kk + tig + 4]);
            qa[3] = __float_as_uint(Qs[(r + g + 8) * QS_STR + kk + tig + 4]);
            #pragma unroll
            for (int nt = 0; nt < 4; nt++) {
                const int c = warp_n * 32 + nt * 8 + g;
                kb2[nt][0] = __float_as_uint(Ks[c * KS_STR + kk + tig]);
                kb2[nt][1] = __float_as_uint(Ks[c * KS_STR + kk + tig + 4]);
            }
            #pragma unroll
            for (int nt = 0; nt < 4; nt++)
                mma_tf32(s4[nt], qa, kb2[nt]);
        }

        // write scaled S to Ps
        #pragma unroll
        for (int nt = 0; nt < 4; nt++) {
            const int row = warp_m * 16 + g;
            const int col = warp_n * 32 + nt * 8 + tig * 2;
            *(float2*)&Ps[row * PS_STR + col] =
                make_float2(s4[nt][0] * scale, s4[nt][1] * scale);
            *(float2*)&Ps[(row + 8) * PS_STR + col] =
                make_float2(s4[nt][2] * scale, s4[nt][3] * scale);
        }
        __syncthreads();

        // online softmax: 4 threads per row
        {
            const int r = t >> 2, q = t & 3;
            const int jhi = (kt == qt) ? r : 63;
            const float mold = mrow[r];
            const int c0 = q * 16;
            float mloc = -1e30f;
            #pragma unroll
            for (int j = 0; j < 16; j++) {
                const int jj = c0 + j;
                if (jj <= jhi) mloc = fmaxf(mloc, Ps[r * PS_STR + jj]);
            }
            mloc = fmaxf(mloc, __shfl_xor_sync(0xffffffffu, mloc, 1));
            mloc = fmaxf(mloc, __shfl_xor_sync(0xffffffffu, mloc, 2));
            const float mnew = fmaxf(mold, mloc);
            float sum = 0.f;
            #pragma unroll
            for (int j = 0; j < 16; j++) {
                const int jj = c0 + j;
                const float p = (jj <= jhi) ? __expf(Ps[r * PS_STR + jj] - mnew) : 0.f;
                Ps[r * PS_STR + jj] = p;
                sum += p;
            }
            sum += __shfl_xor_sync(0xffffffffu, sum, 1);
            sum += __shfl_xor_sync(0xffffffffu, sum, 2);
            if (q == 0) {
                const float al = __expf(mold - mnew);
                lrow[r] = lrow[r] * al + sum;
                mrow[r] = mnew;
                alph[r] = al;
            }
        }
        __syncthreads();

        // rescale accumulators
        const float al0 = alph[warp_m * 16 + g];
        const float al1 = alph[warp_m * 16 + g + 8];
        #pragma unroll
        for (int nt = 0; nt < 8; nt++) {
            oacc[nt][0] *= al0; oacc[nt][1] *= al0;
            oacc[nt][2] *= al1; oacc[nt][3] *= al1;
        }

        // GEMM2: O += P(64x64) @ V(64x128), 8 k-steps
        #pragma unroll
        for (int ks = 0; ks < 8; ks++) {
            const int kk = ks * 8;
            uint32_t pa[4], vb2[8][2];
            const int r = warp_m * 16;
            pa[0] = __float_as_uint(Ps[(r + g    ) * PS_STR + kk + tig]);
            pa[1] = __float_as_uint(Ps[(r + g + 8) * PS_STR + kk + tig]);
            pa[2] = __float_as_uint(Ps[(r + g    ) * PS_STR + kk + tig + 4]);
            pa[3] = __float_as_uint(Ps[(r + g + 8) * PS_STR + kk + tig + 4]);
            #pragma unroll
            for (int nt = 0; nt < 8; nt++) {
                const int c = warp_n * 64 + nt * 8 + g;
                vb2[nt][0] = __float_as_uint(Vs[(kk + tig    ) * VS_STR + c]);
                vb2[nt][1] = __float_as_uint(Vs[(kk + tig + 4) * VS_STR + c]);
            }
            #pragma unroll
            for (int nt = 0; nt < 8; nt++)
                mma_tf32(oacc[nt], pa, vb2[nt]);
        }
        __syncthreads();
    }

    // epilogue: normalize and write ctx [s][b][h*HD + d]
    const float inv0 = 1.f / lrow[warp_m * 16 + g];
    const float inv1 = 1.f / lrow[warp_m * 16 + g + 8];
    const int r0 = i0 + warp_m * 16 + g;
    #pragma unroll
    for (int nt = 0; nt < 8; nt++) {
        const int col = warp_n * 64 + nt * 8 + tig * 2;
        float* op0 = O + ((size_t)r0 * BB + b) * HID + h * HD + col;
        float* op1 = O + ((size_t)(r0 + 8) * BB + b) * HID + h * HD + col;
        *(float2*)op0 = make_float2(oacc[nt][0] * inv0, oacc[nt][1] * inv0);
        *(float2*)op1 = make_float2(oacc[nt][2] * inv1, oacc[nt][3] * inv1);
    }
}

// ------------------------------- launch -------------------------------------
extern "C" void kernel_launch(void* const* d_in, const int* in_sizes, int n_in,
                              void* d_out, int out_size)
{
    const float* hidden = (const float*)d_in[0];
    const float* rope    = (const float*)d_in[2];
    const float* W_qkv   = (const float*)d_in[3];
    const float* b_qkv   = (const float*)d_in[4];
    const float* W_dense = (const float*)d_in[5];
    float* out = (float*)d_out;

    float *mixed, *Qb, *Kb, *Vb, *ctx;
    cudaGetSymbolAddress((void**)&mixed, g_mixed);
    cudaGetSymbolAddress((void**)&Qb,    g_Q);
    cudaGetSymbolAddress((void**)&Kb,    g_K);
    cudaGetSymbolAddress((void**)&Vb,    g_V);
    cudaGetSymbolAddress((void**)&ctx,   g_ctx);

    const size_t fa_smem = FA_SMEM_FLOATS * sizeof(float);
    cudaFuncSetAttribute(flash_mma_kernel,
                         cudaFuncAttributeMaxDynamicSharedMemorySize,
                         (int)fa_smem);

    // 1) mixed = hidden @ W_qkv + b_qkv
    {
        dim3 grid(QKVN / 128, MTOK / 128);
        mma_gemm_kernel<true><<<grid, 256>>>(hidden, W_qkv, b_qkv, mixed,
                                             MTOK, QKVN, HID);
    }
    // 2) rotary + repack
    {
        dim3 grid(MTOK, NH + 2 * NG);
        rotary_repack_kernel<<<grid, 128>>>(mixed, rope, Qb, Kb, Vb);
    }
    // 3) flash attention -> ctx
    {
        dim3 grid(SQ / 64, NH, BB);
        flash_mma_kernel<<<grid, 256, fa_smem>>>(Qb, Kb, Vb, ctx);
    }
    // 4) out = ctx @ W_dense
    {
        dim3 grid(HID / 128, MTOK / 128);
        mma_gemm_kernel<false><<<grid, 256>>>(ctx, W_dense, nullptr, out,
                                              MTOK, HID, HID);
    }
}

// round 7
// speedup vs baseline: 3.4183x; 1.5177x over previous
#include <cuda_runtime.h>
#include <cuda_bf16.h>
#include <cstdint>

// Problem constants
#define SQ   2048
#define BB   2
#define HID  4096
#define NH   32
#define HD   128
#define NG   2
#define QKVN 4608      // NH*HD + 2*NG*HD
#define MTOK 4096      // SQ*B tokens

// ------------------------- scratch (device globals) -------------------------
__device__ float g_mixed[(size_t)MTOK * QKVN];
__device__ float g_Q[(size_t)BB * NH * SQ * HD];
__device__ float g_K[(size_t)BB * NG * SQ * HD];
__device__ float g_V[(size_t)BB * NG * SQ * HD];
__device__ float g_ctx[(size_t)MTOK * HID];

// --------------------------- tf32 / async helpers ---------------------------
__device__ __forceinline__ float to_tf32(float x) {
    uint32_t r;
    asm("cvt.rna.tf32.f32 %0, %1;" : "=r"(r) : "f"(x));
    return __uint_as_float(r);
}
__device__ __forceinline__ uint32_t f2tf(float x) {
    uint32_t r;
    asm("cvt.rna.tf32.f32 %0, %1;" : "=r"(r) : "f"(x));
    return r;
}

__device__ __forceinline__ void cp_async16(void* smem_dst, const void* gmem_src) {
    uint32_t s = (uint32_t)__cvta_generic_to_shared(smem_dst);
    asm volatile("cp.async.cg.shared.global [%0], [%1], 16;\n"
                 :: "r"(s), "l"(gmem_src));
}
__device__ __forceinline__ void cp_commit() {
    asm volatile("cp.async.commit_group;\n");
}
template<int N>
__device__ __forceinline__ void cp_wait() {
    asm volatile("cp.async.wait_group %0;\n" :: "n"(N));
}

// D += A@B ; m16n8k8 tf32
__device__ __forceinline__ void mma_tf32(float* c, const uint32_t* a, const uint32_t* b) {
    asm volatile(
        "mma.sync.aligned.m16n8k8.row.col.f32.tf32.tf32.f32 "
        "{%0,%1,%2,%3},{%4,%5,%6,%7},{%8,%9},{%0,%1,%2,%3};"
        : "+f"(c[0]), "+f"(c[1]), "+f"(c[2]), "+f"(c[3])
        : "r"(a[0]), "r"(a[1]), "r"(a[2]), "r"(a[3]),
          "r"(b[0]), "r"(b[1]));
}

// ------------------------- tf32 tensor-core GEMM ----------------------------
// C = A@B (+bias). A [M,K] row-major, B [K,N] row-major.
// 128x128 block, BK=32, double-buffered cp.async, 256 thr (8 warps, 4m x 2n).
// smem (dynamic): Am[2][128][36] raw fp32, Bs[2][32][136] raw fp32.
#define GM_AM_STRIDE 36
#define GM_BS_STRIDE 136
#define GM_AM_TILE   (128 * GM_AM_STRIDE)   // 4608 floats
#define GM_BS_TILE   (32 * GM_BS_STRIDE)    // 4352 floats
#define GM_SMEM_FLOATS (2 * GM_AM_TILE + 2 * GM_BS_TILE)

template<bool BIAS>
__global__ __launch_bounds__(256) void mma_gemm_kernel(
    const float* __restrict__ A, const float* __restrict__ B,
    const float* __restrict__ bias, float* __restrict__ C,
    int M, int N, int K)
{
    extern __shared__ __align__(16) float sm[];
    float* AmP = sm;                       // [2][128][36]
    float* BsP = sm + 2 * GM_AM_TILE;      // [2][32][136]

    const int t    = threadIdx.x;
    const int w    = t >> 5;
    const int lane = t & 31;
    const int g    = lane >> 2;
    const int tig  = lane & 3;
    const int warp_m = w & 3;       // 0..3 -> 32-row strip
    const int warp_n = w >> 2;      // 0..1 -> 64-col strip
    const int m0 = blockIdx.y * 128;
    const int n0 = blockIdx.x * 128;

    float acc[2][8][4];
    #pragma unroll
    for (int mt = 0; mt < 2; mt++)
        #pragma unroll
        for (int nt = 0; nt < 8; nt++)
            #pragma unroll
            for (int i = 0; i < 4; i++) acc[mt][nt][i] = 0.f;

    const int arow = t >> 3;            // 0..31
    const int acol = (t & 7) * 4;       // 0,4,..,28
    const int brow = t >> 5;            // 0..7
    const int bcol = (t & 31) * 4;      // 0..124

    // issue one k-chunk's tile loads into buffer s
    auto issue_tiles = [&](int k0, int s) {
        float* Am = AmP + s * GM_AM_TILE;
        float* Bs = BsP + s * GM_BS_TILE;
        #pragma unroll
        for (int p = 0; p < 4; p++) {
            cp_async16(&Am[(arow + p * 32) * GM_AM_STRIDE + acol],
                       A + (size_t)(m0 + arow + p * 32) * K + k0 + acol);
        }
        #pragma unroll
        for (int p = 0; p < 4; p++) {
            cp_async16(&Bs[(brow + p * 8) * GM_BS_STRIDE + bcol],
                       B + (size_t)(k0 + brow + p * 8) * N + n0 + bcol);
        }
    };

    issue_tiles(0, 0);
    cp_commit();

    int buf = 0;
    for (int k0 = 0; k0 < K; k0 += 32) {
        const bool has_next = (k0 + 32 < K);
        if (has_next) { issue_tiles(k0 + 32, buf ^ 1); cp_commit(); }
        if (has_next) cp_wait<1>(); else cp_wait<0>();
        __syncthreads();

        const float* Am = AmP + buf * GM_AM_TILE;
        const float* Bs = BsP + buf * GM_BS_TILE;

        #pragma unroll
        for (int ks = 0; ks < 4; ks++) {
            const int kk = ks * 8;
            uint32_t a[2][4], bf[8][2];
            #pragma unroll
            for (int mt = 0; mt < 2; mt++) {
                const int r = warp_m * 32 + mt * 16;
                a[mt][0] = f2tf(Am[(r + g    ) * GM_AM_STRIDE + kk + tig]);
                a[mt][1] = f2tf(Am[(r + g + 8) * GM_AM_STRIDE + kk + tig]);
                a[mt][2] = f2tf(Am[(r + g    ) * GM_AM_STRIDE + kk + tig + 4]);
                a[mt][3] = f2tf(Am[(r + g + 8) * GM_AM_STRIDE + kk + tig + 4]);
            }
            #pragma unroll
            for (int nt = 0; nt < 8; nt++) {
                const int c = warp_n * 64 + nt * 8 + g;
                bf[nt][0] = f2tf(Bs[(kk + tig    ) * GM_BS_STRIDE + c]);
                bf[nt][1] = f2tf(Bs[(kk + tig + 4) * GM_BS_STRIDE + c]);
            }
            #pragma unroll
            for (int mt = 0; mt < 2; mt++)
                #pragma unroll
                for (int nt = 0; nt < 8; nt++)
                    mma_tf32(acc[mt][nt], a[mt], bf[nt]);
        }
        __syncthreads();
        buf ^= 1;
    }

    #pragma unroll
    for (int mt = 0; mt < 2; mt++) {
        const int r0 = m0 + warp_m * 32 + mt * 16 + g;
        #pragma unroll
        for (int nt = 0; nt < 8; nt++) {
            const int col = n0 + warp_n * 64 + nt * 8 + tig * 2;
            float b0 = 0.f, b1 = 0.f;
            if (BIAS) { b0 = bias[col]; b1 = bias[col + 1]; }
            float2 v0 = make_float2(acc[mt][nt][0] + b0, acc[mt][nt][1] + b1);
            float2 v1 = make_float2(acc[mt][nt][2] + b0, acc[mt][nt][3] + b1);
            *(float2*)&C[(size_t)r0 * N + col]       = v0;
            *(float2*)&C[(size_t)(r0 + 8) * N + col] = v1;
        }
    }
}

// ------------------- rotary + repack (mixed -> Q/K/V) -----------------------
__global__ void rotary_repack_kernel(
    const float* __restrict__ mixed, const float* __restrict__ rope,
    float* __restrict__ Q, float* __restrict__ Kd, float* __restrict__ Vd)
{
    const int m  = blockIdx.x;
    const int hh = blockIdx.y;
    const int s  = m >> 1;
    const int b  = m & 1;
    const int d  = threadIdx.x;

    const float* src;
    float* dst;
    bool rot;
    if (hh < NH) {
        src = mixed + (size_t)m * QKVN + hh * HD;
        dst = Q + ((size_t)(b * NH + hh) * SQ + s) * HD;
        rot = true;
    } else if (hh < NH + NG) {
        const int gg = hh - NH;
        src = mixed + (size_t)m * QKVN + NH * HD + gg * HD;
        dst = Kd + ((size_t)(b * NG + gg) * SQ + s) * HD;
        rot = true;
    } else {
        const int gg = hh - NH - NG;
        src = mixed + (size_t)m * QKVN + NH * HD + NG * HD + gg * HD;
        dst = Vd + ((size_t)(b * NG + gg) * SQ + s) * HD;
        rot = false;
    }

    if (!rot) { dst[d] = src[d]; return; }

    if (d < 32) {
        const float x0 = src[2 * d];
        const float x1 = src[2 * d + 1];
        const float c  = rope[(size_t)s * 64 + 2 * d];
        const float sn = rope[(size_t)s * 64 + 2 * d + 1];
        dst[2 * d]     = x0 * c - x1 * sn;
        dst[2 * d + 1] = x1 * c + x0 * sn;
    } else if (d >= 64) {
        dst[d] = src[d];
    }
}

// --------------------- flash attention (tf32 mma) ---------------------------
// BM=BN=64, 256 threads (8 warps: 4m x 2n). grid (SQ/64, NH, B).
// K/V tiles double-buffered via cp.async; raw fp32 in smem, cvt at gather.
#define QS_STR 132
#define KS_STR 132
#define VS_STR 136
#define PS_STR 68
#define KS_TILE (64 * KS_STR)
#define VS_TILE (64 * VS_STR)
#define FA_SMEM_FLOATS (64*QS_STR + 2*KS_TILE + 2*VS_TILE + 64*PS_STR + 192)

__global__ __launch_bounds__(256) void flash_mma_kernel(
    const float* __restrict__ Q, const float* __restrict__ K,
    const float* __restrict__ V, float* __restrict__ O)
{
    extern __shared__ __align__(16) float smf[];
    float* Qs   = smf;                       // [64][132] (tf32-rounded values)
    float* KsP  = Qs + 64 * QS_STR;          // [2][64][132] raw fp32
    float* VsP  = KsP + 2 * KS_TILE;         // [2][64][136] raw fp32
    float* Ps   = VsP + 2 * VS_TILE;         // [64][68]
    float* mrow = Ps + 64 * PS_STR;
    float* lrow = mrow + 64;
    float* alph = lrow + 64;

    const int t    = threadIdx.x;
    const int w    = t >> 5;
    const int lane = t & 31;
    const int g    = lane >> 2;
    const int tig  = lane & 3;
    const int warp_m = w & 3;       // 16-row strip of S / O
    const int warp_n = w >> 2;      // 32-col strip of S, 64-col strip of O
    const int qt = blockIdx.x;
    const int h  = blockIdx.y;
    const int b  = blockIdx.z;
    const int gk = h >> 4;          // rep = 16
    const int i0 = qt * 64;

    const float* Qb = Q + ((size_t)(b * NH + h) * SQ + i0) * HD;
    const float* Kb = K + ((size_t)(b * NG + gk) * SQ) * HD;
    const float* Vb = V + ((size_t)(b * NG + gk) * SQ) * HD;

    const int r0c = t >> 5;             // 0..7
    const int cc  = (t & 31) * 4;       // 0..124

    // prefetch KV tile 0
    auto issue_kv = [&](int kt, int s) {
        const int j0 = kt * 64;
        float* Ks = KsP + s * KS_TILE;
        float* Vs = VsP + s * VS_TILE;
        #pragma unroll
        for (int p = 0; p < 8; p++) {
            const int r = r0c + p * 8;
            cp_async16(&Ks[r * KS_STR + cc], Kb + (size_t)(j0 + r) * HD + cc);
            cp_async16(&Vs[r * VS_STR + cc], Vb + (size_t)(j0 + r) * HD + cc);
        }
    };
    issue_kv(0, 0);
    cp_commit();

    // load Q tile (row-major, tf32-rounded) — overlaps with KV prefetch
    {
        #pragma unroll
        for (int p = 0; p < 8; p++) {
            const int r = r0c + p * 8;
            float4 v = *(const float4*)(Qb + (size_t)r * HD + cc);
            float4 tv = make_float4(to_tf32(v.x), to_tf32(v.y), to_tf32(v.z), to_tf32(v.w));
            *(float4*)&Qs[r * QS_STR + cc] = tv;
        }
    }
    if (t < 64) { mrow[t] = -1e30f; lrow[t] = 0.f; }

    float oacc[8][4];
    #pragma unroll
    for (int nt = 0; nt < 8; nt++)
        #pragma unroll
        for (int i = 0; i < 4; i++) oacc[nt][i] = 0.f;

    const float scale = 0.08838834764831845f;   // 1/sqrt(128)

    int buf = 0;
    for (int kt = 0; kt <= qt; kt++) {
        const bool has_next = (kt < qt);
        if (has_next) { issue_kv(kt + 1, buf ^ 1); cp_commit(); }
        if (has_next) cp_wait<1>(); else cp_wait<0>();
        __syncthreads();

        const float* Ks = KsP + buf * KS_TILE;
        const float* Vs = VsP + buf * VS_TILE;

        // GEMM1: S(64x64) = Q @ K^T, K-dim = HD = 128 (16 k-steps)
        float s4[4][4];
        #pragma unroll
        for (int nt = 0; nt < 4; nt++)
            #pragma unroll
            for (int i = 0; i < 4; i++) s4[nt][i] = 0.f;

        #pragma unroll
        for (int ks = 0; ks < 16; ks++) {
            const int kk = ks * 8;
            uint32_t qa[4], kb2[4][2];
            const int r = warp_m * 16;
            qa[0] = __float_as_uint(Qs[(r + g    ) * QS_STR + kk + tig]);
            qa[1] = __float_as_uint(Qs[(r + g + 8) * QS_STR + kk + tig]);
            qa[2] = __float_as_uint(Qs[(r + g    ) * QS_STR + kk + tig + 4]);
            qa[3] = __float_as_uint(Qs[(r + g + 8) * QS_STR + kk + tig + 4]);
            #pragma unroll
            for (int nt = 0; nt < 4; nt++) {
                const int c = warp_n * 32 + nt * 8 + g;
                kb2[nt][0] = f2tf(Ks[c * KS_STR + kk + tig]);
                kb2[nt][1] = f2tf(Ks[c * KS_STR + kk + tig + 4]);
            }
            #pragma unroll
            for (int nt = 0; nt < 4; nt++)
                mma_tf32(s4[nt], qa, kb2[nt]);
        }

        // write scaled S to Ps
        #pragma unroll
        for (int nt = 0; nt < 4; nt++) {
            const int row = warp_m * 16 + g;
            const int col = warp_n * 32 + nt * 8 + tig * 2;
            *(float2*)&Ps[row * PS_STR + col] =
                make_float2(s4[nt][0] * scale, s4[nt][1] * scale);
            *(float2*)&Ps[(row + 8) * PS_STR + col] =
                make_float2(s4[nt][2] * scale, s4[nt][3] * scale);
        }
        __syncthreads();

        // online softmax: 4 threads per row
        {
            const int r = t >> 2, q = t & 3;
            const int jhi = (kt == qt) ? r : 63;
            const float mold = mrow[r];
            const int c0 = q * 16;
            float mloc = -1e30f;
            #pragma unroll
            for (int j = 0; j < 16; j++) {
                const int jj = c0 + j;
                if (jj <= jhi) mloc = fmaxf(mloc, Ps[r * PS_STR + jj]);
            }
            mloc = fmaxf(mloc, __shfl_xor_sync(0xffffffffu, mloc, 1));
            mloc = fmaxf(mloc, __shfl_xor_sync(0xffffffffu, mloc, 2));
            const float mnew = fmaxf(mold, mloc);
            float sum = 0.f;
            #pragma unroll
            for (int j = 0; j < 16; j++) {
                const int jj = c0 + j;
                const float p = (jj <= jhi) ? __expf(Ps[r * PS_STR + jj] - mnew) : 0.f;
                Ps[r * PS_STR + jj] = p;
                sum += p;
            }
            sum += __shfl_xor_sync(0xffffffffu, sum, 1);
            sum += __shfl_xor_sync(0xffffffffu, sum, 2);
            if (q == 0) {
                const float al = __expf(mold - mnew);
                lrow[r] = lrow[r] * al + sum;
                mrow[r] = mnew;
                alph[r] = al;
            }
        }
        __syncthreads();

        // rescale accumulators
        const float al0 = alph[warp_m * 16 + g];
        const float al1 = alph[warp_m * 16 + g + 8];
        #pragma unroll
        for (int nt = 0; nt < 8; nt++) {
            oacc[nt][0] *= al0; oacc[nt][1] *= al0;
            oacc[nt][2] *= al1; oacc[nt][3] *= al1;
        }

        // GEMM2: O += P(64x64) @ V(64x128), 8 k-steps
        #pragma unroll
        for (int ks = 0; ks < 8; ks++) {
            const int kk = ks * 8;
            uint32_t pa[4], vb2[8][2];
            const int r = warp_m * 16;
            pa[0] = __float_as_uint(Ps[(r + g    ) * PS_STR + kk + tig]);
            pa[1] = __float_as_uint(Ps[(r + g + 8) * PS_STR + kk + tig]);
            pa[2] = __float_as_uint(Ps[(r + g    ) * PS_STR + kk + tig + 4]);
            pa[3] = __float_as_uint(Ps[(r + g + 8) * PS_STR + kk + tig + 4]);
            #pragma unroll
            for (int nt = 0; nt < 8; nt++) {
                const int c = warp_n * 64 + nt * 8 + g;
                vb2[nt][0] = f2tf(Vs[(kk + tig    ) * VS_STR + c]);
                vb2[nt][1] = f2tf(Vs[(kk + tig + 4) * VS_STR + c]);
            }
            #pragma unroll
            for (int nt = 0; nt < 8; nt++)
                mma_tf32(oacc[nt], pa, vb2[nt]);
        }
        __syncthreads();
        buf ^= 1;
    }

    // epilogue: normalize and write ctx [s][b][h*HD + d]
    const float inv0 = 1.f / lrow[warp_m * 16 + g];
    const float inv1 = 1.f / lrow[warp_m * 16 + g + 8];
    const int r0 = i0 + warp_m * 16 + g;
    #pragma unroll
    for (int nt = 0; nt < 8; nt++) {
        const int col = warp_n * 64 + nt * 8 + tig * 2;
        float* op0 = O + ((size_t)r0 * BB + b) * HID + h * HD + col;
        float* op1 = O + ((size_t)(r0 + 8) * BB + b) * HID + h * HD + col;
        *(float2*)op0 = make_float2(oacc[nt][0] * inv0, oacc[nt][1] * inv0);
        *(float2*)op1 = make_float2(oacc[nt][2] * inv1, oacc[nt][3] * inv1);
    }
}

// ------------------------------- launch -------------------------------------
extern "C" void kernel_launch(void* const* d_in, const int* in_sizes, int n_in,
                              void* d_out, int out_size)
{
    const float* hidden = (const float*)d_in[0];
    const float* rope    = (const float*)d_in[2];
    const float* W_qkv   = (const float*)d_in[3];
    const float* b_qkv   = (const float*)d_in[4];
    const float* W_dense = (const float*)d_in[5];
    float* out = (float*)d_out;

    float *mixed, *Qb, *Kb, *Vb, *ctx;
    cudaGetSymbolAddress((void**)&mixed, g_mixed);
    cudaGetSymbolAddress((void**)&Qb,    g_Q);
    cudaGetSymbolAddress((void**)&Kb,    g_K);
    cudaGetSymbolAddress((void**)&Vb,    g_V);
    cudaGetSymbolAddress((void**)&ctx,   g_ctx);

    const size_t gm_smem = GM_SMEM_FLOATS * sizeof(float);
    const size_t fa_smem = FA_SMEM_FLOATS * sizeof(float);
    cudaFuncSetAttribute(mma_gemm_kernel<true>,
                         cudaFuncAttributeMaxDynamicSharedMemorySize, (int)gm_smem);
    cudaFuncSetAttribute(mma_gemm_kernel<false>,
                         cudaFuncAttributeMaxDynamicSharedMemorySize, (int)gm_smem);
    cudaFuncSetAttribute(flash_mma_kernel,
                         cudaFuncAttributeMaxDynamicSharedMemorySize, (int)fa_smem);

    // 1) mixed = hidden @ W_qkv + b_qkv
    {
        dim3 grid(QKVN / 128, MTOK / 128);
        mma_gemm_kernel<true><<<grid, 256, gm_smem>>>(hidden, W_qkv, b_qkv, mixed,
                                                      MTOK, QKVN, HID);
    }
    // 2) rotary + repack
    {
        dim3 grid(MTOK, NH + 2 * NG);
        rotary_repack_kernel<<<grid, 128>>>(mixed, rope, Qb, Kb, Vb);
    }
    // 3) flash attention -> ctx
    {
        dim3 grid(SQ / 64, NH, BB);
        flash_mma_kernel<<<grid, 256, fa_smem>>>(Qb, Kb, Vb, ctx);
    }
    // 4) out = ctx @ W_dense
    {
        dim3 grid(HID / 128, MTOK / 128);
        mma_gemm_kernel<false><<<grid, 256, gm_smem>>>(ctx, W_dense, nullptr, out,
                                                       MTOK, HID, HID);
    }
}